// round 1
// baseline (speedup 1.0000x reference)
#include <cuda_runtime.h>
#include <stdint.h>

// RadialTokenizer: per (batch=256, channel=3) image 256x256:
//   img = floor((x*0.5+0.5)*255)  -> integer values in [127,254] (128 bins)
//   for 16 rings (annuli of width 8 around center (128,128)):
//     mean, std (ddof=0), median over ring pixels
// out[b, r, 0:3]=mean, [3:6]=std, [6:9]=median   (256,16,9) fp32
//
// Strategy: exact 128-bin histogram per (b,c,ring) built in per-lane private
// byte counters in shared memory (conflict-free, no atomics). Mean/std/median
// all derived from the histogram. Pixel offset lists (ring-packed, u16) are
// rebuilt deterministically each launch by 3 cheap init kernels.

#define HH 256
#define WW 256
#define NR 16
#define MAXPIX 53248   // > number of lattice points with 0 < d2 <= 128^2 (~51472)

__device__ uint16_t g_off[MAXPIX];      // pixel linear offsets, grouped by ring, sorted (y,x)
__device__ int g_ringbase[NR + 1];      // start of each ring in g_off
__device__ int g_rowcnt[HH * NR];       // per-(row,ring) pixel counts
__device__ int g_rowstart[HH * NR];     // per-(row,ring) start position in g_off

// Exact integer ring classification: ring i <=> 64*i^2 < d2 <= 64*(i+1)^2.
// Center pixel (d2==0) excluded (matches "dist > 0" for ring 0).
__device__ __forceinline__ int ring_of(int x, int y) {
    int dx = x - 128, dy = y - 128;
    int d2 = dx * dx + dy * dy;
    if (d2 == 0 || d2 > 16384) return -1;
    int k = 1;
    while (64 * k * k < d2) k++;   // k = smallest int with 64k^2 >= d2  (k <= 16)
    return k - 1;
}

// ---------------- init kernels (run every launch; deterministic) ----------------

__global__ void k_count() {
    __shared__ int cnt[NR];
    int x = threadIdx.x, y = blockIdx.x;
    if (x < NR) cnt[x] = 0;
    __syncthreads();
    int r = ring_of(x, y);
    if (r >= 0) atomicAdd(&cnt[r], 1);
    __syncthreads();
    if (x < NR) g_rowcnt[y * NR + x] = cnt[x];
}

__global__ void k_prefix() {
    int t = threadIdx.x;
    __shared__ int tot[NR];
    __shared__ int base[NR + 1];
    if (t < NR) {
        int s = 0;
        for (int y = 0; y < HH; y++) s += g_rowcnt[y * NR + t];
        tot[t] = s;
    }
    __syncthreads();
    if (t == 0) {
        int run = 0;
        for (int r = 0; r < NR; r++) { base[r] = run; g_ringbase[r] = run; run += tot[r]; }
        base[NR] = run;
        g_ringbase[NR] = run;
    }
    __syncthreads();
    if (t < NR) {
        int run = base[t];
        for (int y = 0; y < HH; y++) {
            g_rowstart[y * NR + t] = run;
            run += g_rowcnt[y * NR + t];
        }
    }
}

__global__ void k_scatter() {
    __shared__ int rid[WW];
    int x = threadIdx.x, y = blockIdx.x;
    int r = ring_of(x, y);
    rid[x] = r;
    __syncthreads();
    if (r >= 0) {
        int rank = 0;
        #pragma unroll 8
        for (int i = 0; i < WW; i++)
            rank += (i < x && rid[i] == r) ? 1 : 0;
        g_off[g_rowstart[y * NR + r] + rank] = (uint16_t)(y * WW + x);
    }
}

// ---------------- main kernel: warp per (b, c, ring) ----------------
// Block = 256 threads = 8 warps. Ring pairing (k, 15-k) => every block has an
// identical pixel budget (load balance). 32KB smem = 8 warps * 4KB lane-hist.
// Hist byte addr = (bin>>2)*128 + lane*4 + (bin&3)  -> bank == lane, conflict-free.

__global__ void __launch_bounds__(256) k_main(const float* __restrict__ img,
                                              float* __restrict__ out) {
    __shared__ uint8_t hist[8][4096];

    const int lane = threadIdx.x & 31;
    const int w    = threadIdx.x >> 5;
    const int bx   = blockIdx.x;
    const int bc   = bx >> 1;       // 0..767 = b*3 + c
    const int half = bx & 1;

    const int p     = w >> 1;
    const int base8 = half * 4 + p;           // 0..7
    const int ring  = (w & 1) ? (15 - base8) : base8;

    uint8_t* h = hist[w];

    // zero this warp's 4KB histogram
    uint4* h4 = (uint4*)h;
    uint4 z; z.x = z.y = z.z = z.w = 0u;
    #pragma unroll
    for (int j = 0; j < 8; j++) h4[j * 32 + lane] = z;
    __syncwarp();

    const int start = g_ringbase[ring];
    const int n     = g_ringbase[ring + 1] - start;
    const uint16_t* __restrict__ offs = g_off + start;
    const float* __restrict__ ip = img + (size_t)bc * (HH * WW);

    const int hb_lane = lane << 2;
    const int nfull = n & ~31;

    #pragma unroll 4
    for (int basei = 0; basei < nfull; basei += 32) {
        int off  = offs[basei + lane];
        float xv = __ldcs(ip + off);
        // replicate jax exactly: (x*0.5 + 0.5) * 255, then floor (unfused ops)
        float t = __fmul_rn(xv, 0.5f);
        t = __fadd_rn(t, 0.5f);
        t = __fmul_rn(t, 255.0f);
        int bin = __float2int_rd(t) - 127;                 // 0..127
        int a = ((bin >> 2) << 7) + hb_lane + (bin & 3);
        h[a] += 1;
    }
    if (nfull + lane < n) {
        int off  = offs[nfull + lane];
        float xv = __ldcs(ip + off);
        float t = __fmul_rn(xv, 0.5f);
        t = __fadd_rn(t, 0.5f);
        t = __fmul_rn(t, 255.0f);
        int bin = __float2int_rd(t) - 127;
        int a = ((bin >> 2) << 7) + hb_lane + (bin & 3);
        h[a] += 1;
    }
    __syncwarp();

    // Reduce: lane l owns bins 4l..4l+3; sum the byte counters of all 32 lanes.
    // Word (g*32 + j) holds bins {4g..4g+3} of owner-lane j. Stagger j to avoid
    // bank conflicts.
    const uint32_t* hw = (const uint32_t*)h;
    uint32_t a02 = 0, a13 = 0;
    #pragma unroll
    for (int jj = 0; jj < 32; jj++) {
        int j = (jj + lane) & 31;
        uint32_t v = hw[lane * 32 + j];
        a02 += v & 0x00FF00FFu;          // bytes 0,2 as packed u16
        a13 += (v >> 8) & 0x00FF00FFu;   // bytes 1,3 as packed u16
    }
    int h0 = (int)(a02 & 0xFFFFu), h2 = (int)(a02 >> 16);
    int h1 = (int)(a13 & 0xFFFFu), h3 = (int)(a13 >> 16);

    const int b0 = lane * 4;
    int sl  = h0 + h1 + h2 + h3;
    int sb  = h0 * b0 + h1 * (b0 + 1) + h2 * (b0 + 2) + h3 * (b0 + 3);
    int sb2 = h0 * b0 * b0 + h1 * (b0 + 1) * (b0 + 1)
            + h2 * (b0 + 2) * (b0 + 2) + h3 * (b0 + 3) * (b0 + 3);

    int sumb  = __reduce_add_sync(0xffffffffu, sb);
    int sumb2 = __reduce_add_sync(0xffffffffu, sb2);

    // inclusive scan of per-lane group totals -> CDF
    int sc = sl;
    #pragma unroll
    for (int d = 1; d < 32; d <<= 1) {
        int t2 = __shfl_up_sync(0xffffffffu, sc, d);
        if (lane >= d) sc += t2;
    }
    int cb = sc - sl;   // cumulative count before this lane's 4 bins

    int k1 = (n - 1) >> 1, k2 = n >> 1;   // 0-indexed middle ranks
    int c1 = 1 << 30, c2 = 1 << 30;
    {
        int t1 = k1 + 1;
        if (cb < t1 && t1 <= sc) {
            if      (cb + h0 >= t1)           c1 = b0;
            else if (cb + h0 + h1 >= t1)      c1 = b0 + 1;
            else if (cb + h0 + h1 + h2 >= t1) c1 = b0 + 2;
            else                              c1 = b0 + 3;
        }
        int t2r = k2 + 1;
        if (cb < t2r && t2r <= sc) {
            if      (cb + h0 >= t2r)           c2 = b0;
            else if (cb + h0 + h1 >= t2r)      c2 = b0 + 1;
            else if (cb + h0 + h1 + h2 >= t2r) c2 = b0 + 2;
            else                               c2 = b0 + 3;
        }
    }
    int m1 = __reduce_min_sync(0xffffffffu, c1);
    int m2 = __reduce_min_sync(0xffffffffu, c2);

    if (lane == 0) {
        double dn = (double)n;
        double mb = (double)sumb / dn;
        double mean = 127.0 + mb;
        double var = (double)sumb2 / dn - mb * mb;
        double sd = sqrt(var > 0.0 ? var : 0.0);
        double med = 127.0 + 0.5 * (double)(m1 + m2);
        int b = bc / 3, c = bc - b * 3;
        int o = b * (NR * 9) + ring * 9 + c;
        out[o]     = (float)mean;
        out[o + 3] = (float)sd;
        out[o + 6] = (float)med;
    }
}

extern "C" void kernel_launch(void* const* d_in, const int* in_sizes, int n_in,
                              void* d_out, int out_size) {
    const float* img = (const float*)d_in[0];
    float* out = (float*)d_out;

    // deterministic offset-table rebuild (cheap, graph-capturable)
    k_count<<<HH, WW>>>();
    k_prefix<<<1, 32>>>();
    k_scatter<<<HH, WW>>>();

    // 768 (b,c) pairs x 2 half-blocks, 8 warps each (one warp per ring)
    k_main<<<1536, 256>>>(img, out);
}

// round 2
// speedup vs baseline: 1.2332x; 1.2332x over previous
#include <cuda_runtime.h>
#include <stdint.h>

// RadialTokenizer: per (batch=256, channel=3) image 256x256:
//   img = floor((x*0.5+0.5)*255)  -> integer values in [127,254] (128 bins)
//   for 16 rings (annuli of width 8 around center (128,128)):
//     mean, std (ddof=0), median over ring pixels
// out[b, r, 0:3]=mean, [3:6]=std, [6:9]=median   (256,16,9) fp32
//
// Exact 128-bin histogram per (b,c,ring) in per-lane private byte counters
// (conflict-free, no atomics). Offset lists rebuilt each launch (graph-safe).

#define HH 256
#define WW 256
#define NR 16
#define MAXPIX 53248

__device__ uint16_t g_off[MAXPIX];      // pixel offsets grouped by ring
__device__ int g_ringbase[NR + 1];
__device__ int g_rowcnt[HH * NR];
__device__ int g_rowstart[HH * NR];

// ring i <=> 64*i^2 < d2 <= 64*(i+1)^2 ; center pixel excluded.
__device__ __forceinline__ int ring_of(int x, int y) {
    int dx = x - 128, dy = y - 128;
    int d2 = dx * dx + dy * dy;
    if (d2 == 0 || d2 > 16384) return -1;
    int k = 1;
    while (64 * k * k < d2) k++;
    return k - 1;
}

// ---------------- init kernels ----------------

__global__ void k_count() {
    __shared__ int cnt[NR];
    int x = threadIdx.x, y = blockIdx.x;
    int lane = x & 31;
    if (x < NR) cnt[x] = 0;
    __syncthreads();
    int r = ring_of(x, y);
    unsigned m = __match_any_sync(0xffffffffu, r);
    if (r >= 0 && (m & ((1u << lane) - 1)) == 0)
        atomicAdd(&cnt[r], __popc(m));
    __syncthreads();
    if (x < NR) g_rowcnt[y * NR + x] = cnt[x];
}

__global__ void k_prefix() {
    int t = threadIdx.x;
    __shared__ int tot[NR];
    __shared__ int base[NR + 1];
    if (t < NR) {
        int s = 0;
        for (int y = 0; y < HH; y++) s += g_rowcnt[y * NR + t];
        tot[t] = s;
    }
    __syncthreads();
    if (t == 0) {
        int run = 0;
        for (int r = 0; r < NR; r++) { base[r] = run; g_ringbase[r] = run; run += tot[r]; }
        g_ringbase[NR] = run;
    }
    __syncthreads();
    if (t < NR) {
        int run = base[t];
        for (int y = 0; y < HH; y++) {
            g_rowstart[y * NR + t] = run;
            run += g_rowcnt[y * NR + t];
        }
    }
}

__global__ void k_scatter() {
    __shared__ int wcnt[8][NR];
    __shared__ int wbase[8][NR];
    int x = threadIdx.x, y = blockIdx.x;
    int lane = x & 31, w = x >> 5;
    int r = ring_of(x, y);
    unsigned m = __match_any_sync(0xffffffffu, r);
    int rank = __popc(m & ((1u << lane) - 1));
    if (x < 8 * NR) ((int*)wcnt)[x] = 0;
    __syncthreads();
    if (r >= 0 && rank == 0) wcnt[w][r] = __popc(m);
    __syncthreads();
    if (x < NR) {
        int run = 0;
        #pragma unroll
        for (int ww = 0; ww < 8; ww++) { wbase[ww][x] = run; run += wcnt[ww][x]; }
    }
    __syncthreads();
    if (r >= 0)
        g_off[g_rowstart[y * NR + r] + wbase[w][r] + rank] = (uint16_t)(y * WW + x);
}

// ---------------- main kernel: warp per (b, c, ring) ----------------
// Block = 8 warps; rings paired (k, 15-k) across the two half-blocks of a
// (b,c) so every block carries an identical pixel budget.
// Hist byte addr = (bin>>2)*128 + lane*4 + (bin&3) -> bank == lane.

__global__ void __launch_bounds__(256) k_main(const float* __restrict__ img,
                                              float* __restrict__ out) {
    __shared__ uint8_t hist[8][4096];

    const int lane = threadIdx.x & 31;
    const int w    = threadIdx.x >> 5;
    const int bx   = blockIdx.x;
    const int bc   = bx >> 1;
    const int half = bx & 1;

    const int base8 = half * 4 + (w >> 1);
    const int ring  = (w & 1) ? (15 - base8) : base8;

    uint8_t* h = hist[w];

    uint4* h4 = (uint4*)h;
    uint4 z; z.x = z.y = z.z = z.w = 0u;
    #pragma unroll
    for (int j = 0; j < 8; j++) h4[j * 32 + lane] = z;
    __syncwarp();

    const int start = g_ringbase[ring];
    const int n     = g_ringbase[ring + 1] - start;
    const uint16_t* __restrict__ offs = g_off + start;
    const float* __restrict__ ip = img + (size_t)bc * (HH * WW);

    const int hb_lane = lane << 2;

    // ---- 256 px per warp-step: 8 independent offset loads, then 8
    // independent image loads (MLP=8), then 8 conflict-free hist updates ----
    const int nfull = n & ~255;
    for (int base = 0; base < nfull; base += 256) {
        int o[8];
        #pragma unroll
        for (int j = 0; j < 8; j++) o[j] = offs[base + j * 32 + lane];
        float v[8];
        #pragma unroll
        for (int j = 0; j < 8; j++) v[j] = __ldcs(ip + o[j]);
        #pragma unroll
        for (int j = 0; j < 8; j++) {
            float t = __fmul_rn(v[j], 0.5f);
            t = __fadd_rn(t, 0.5f);
            t = __fmul_rn(t, 255.0f);
            int bin = __float2int_rd(t) - 127;
            h[((bin & 0x7C) << 5) + hb_lane + (bin & 3)] += 1;
        }
    }
    // tail
    for (int base = nfull; base < n; base += 32) {
        if (base + lane < n) {
            int off = offs[base + lane];
            float t = __fmul_rn(__ldcs(ip + off), 0.5f);
            t = __fadd_rn(t, 0.5f);
            t = __fmul_rn(t, 255.0f);
            int bin = __float2int_rd(t) - 127;
            h[((bin & 0x7C) << 5) + hb_lane + (bin & 3)] += 1;
        }
    }
    __syncwarp();

    // Reduce: lane l owns bins 4l..4l+3; sum byte counters across 32 lanes.
    const uint32_t* hw = (const uint32_t*)h;
    uint32_t a02 = 0, a13 = 0;
    #pragma unroll
    for (int jj = 0; jj < 32; jj++) {
        int j = (jj + lane) & 31;
        uint32_t v = hw[lane * 32 + j];
        a02 += v & 0x00FF00FFu;
        a13 += (v >> 8) & 0x00FF00FFu;
    }
    int h0 = (int)(a02 & 0xFFFFu), h2 = (int)(a02 >> 16);
    int h1 = (int)(a13 & 0xFFFFu), h3 = (int)(a13 >> 16);

    const int b0 = lane * 4;
    int sl  = h0 + h1 + h2 + h3;
    int sb  = h0 * b0 + h1 * (b0 + 1) + h2 * (b0 + 2) + h3 * (b0 + 3);
    int sb2 = h0 * b0 * b0 + h1 * (b0 + 1) * (b0 + 1)
            + h2 * (b0 + 2) * (b0 + 2) + h3 * (b0 + 3) * (b0 + 3);

    int sumb  = __reduce_add_sync(0xffffffffu, sb);
    int sumb2 = __reduce_add_sync(0xffffffffu, sb2);

    int sc = sl;
    #pragma unroll
    for (int d = 1; d < 32; d <<= 1) {
        int t2 = __shfl_up_sync(0xffffffffu, sc, d);
        if (lane >= d) sc += t2;
    }
    int cb = sc - sl;

    int k1 = (n - 1) >> 1, k2 = n >> 1;
    int c1 = 1 << 30, c2 = 1 << 30;
    {
        int t1 = k1 + 1;
        if (cb < t1 && t1 <= sc) {
            if      (cb + h0 >= t1)           c1 = b0;
            else if (cb + h0 + h1 >= t1)      c1 = b0 + 1;
            else if (cb + h0 + h1 + h2 >= t1) c1 = b0 + 2;
            else                              c1 = b0 + 3;
        }
        int t2r = k2 + 1;
        if (cb < t2r && t2r <= sc) {
            if      (cb + h0 >= t2r)           c2 = b0;
            else if (cb + h0 + h1 >= t2r)      c2 = b0 + 1;
            else if (cb + h0 + h1 + h2 >= t2r) c2 = b0 + 2;
            else                               c2 = b0 + 3;
        }
    }
    int m1 = __reduce_min_sync(0xffffffffu, c1);
    int m2 = __reduce_min_sync(0xffffffffu, c2);

    if (lane == 0) {
        double dn = (double)n;
        double mb = (double)sumb / dn;
        double mean = 127.0 + mb;
        double var = (double)sumb2 / dn - mb * mb;
        double sd = sqrt(var > 0.0 ? var : 0.0);
        double med = 127.0 + 0.5 * (double)(m1 + m2);
        int b = bc / 3, c = bc - b * 3;
        int o = b * (NR * 9) + ring * 9 + c;
        out[o]     = (float)mean;
        out[o + 3] = (float)sd;
        out[o + 6] = (float)med;
    }
}

extern "C" void kernel_launch(void* const* d_in, const int* in_sizes, int n_in,
                              void* d_out, int out_size) {
    const float* img = (const float*)d_in[0];
    float* out = (float*)d_out;

    k_count<<<HH, WW>>>();
    k_prefix<<<1, 32>>>();
    k_scatter<<<HH, WW>>>();

    k_main<<<1536, 256>>>(img, out);
}

// round 3
// speedup vs baseline: 1.2842x; 1.0413x over previous
#include <cuda_runtime.h>
#include <stdint.h>

// RadialTokenizer: per (batch=256, channel=3) image 256x256:
//   img = floor((x*0.5+0.5)*255)  -> integers in [127,254] (128 bins)
//   16 rings (annuli width 8 around (128,128)): mean, std, median
// out[b, r, 0:3]=mean, [3:6]=std, [6:9]=median   (256,16,9) fp32
//
// Exact 128-bin histogram per (b,c,ring) in per-lane private byte counters
// (conflict-free, no atomics). One warp = one ring PAIR (k,15-k): every warp
// on the chip processes exactly ~6440 px -> perfect load balance.

#define HH 256
#define WW 256
#define NR 16
#define MAXPIX 53248

__device__ uint16_t g_off[MAXPIX];
__device__ int g_ringbase[NR + 1];
__device__ int g_rowcnt[HH * NR];
__device__ int g_rowstart[HH * NR];

__device__ __forceinline__ int ring_of(int x, int y) {
    int dx = x - 128, dy = y - 128;
    int d2 = dx * dx + dy * dy;
    if (d2 == 0 || d2 > 16384) return -1;
    int k = 1;
    while (64 * k * k < d2) k++;
    return k - 1;
}

// ---------------- init kernels (deterministic, run every launch) ----------------

__global__ void k_count() {
    __shared__ int cnt[NR];
    int x = threadIdx.x, y = blockIdx.x;
    int lane = x & 31;
    if (x < NR) cnt[x] = 0;
    __syncthreads();
    int r = ring_of(x, y);
    unsigned m = __match_any_sync(0xffffffffu, r);
    if (r >= 0 && (m & ((1u << lane) - 1)) == 0)
        atomicAdd(&cnt[r], __popc(m));
    __syncthreads();
    if (x < NR) g_rowcnt[y * NR + x] = cnt[x];
}

__global__ void k_prefix() {
    int t = threadIdx.x;
    __shared__ int tot[NR];
    __shared__ int base[NR + 1];
    if (t < NR) {
        int s = 0;
        for (int y = 0; y < HH; y++) s += g_rowcnt[y * NR + t];
        tot[t] = s;
    }
    __syncthreads();
    if (t == 0) {
        int run = 0;
        for (int r = 0; r < NR; r++) { base[r] = run; g_ringbase[r] = run; run += tot[r]; }
        g_ringbase[NR] = run;
    }
    __syncthreads();
    if (t < NR) {
        int run = base[t];
        for (int y = 0; y < HH; y++) {
            g_rowstart[y * NR + t] = run;
            run += g_rowcnt[y * NR + t];
        }
    }
}

__global__ void k_scatter() {
    __shared__ int wcnt[8][NR];
    __shared__ int wbase[8][NR];
    int x = threadIdx.x, y = blockIdx.x;
    int lane = x & 31, w = x >> 5;
    int r = ring_of(x, y);
    unsigned m = __match_any_sync(0xffffffffu, r);
    int rank = __popc(m & ((1u << lane) - 1));
    if (x < 8 * NR) ((int*)wcnt)[x] = 0;
    __syncthreads();
    if (r >= 0 && rank == 0) wcnt[w][r] = __popc(m);
    __syncthreads();
    if (x < NR) {
        int run = 0;
        #pragma unroll
        for (int ww = 0; ww < 8; ww++) { wbase[ww][x] = run; run += wcnt[ww][x]; }
    }
    __syncthreads();
    if (r >= 0)
        g_off[g_rowstart[y * NR + r] + wbase[w][r] + rank] = (uint16_t)(y * WW + x);
}

// ---------------- main kernel ----------------
// Block = 4 warps (16KB smem -> 13 blocks/SM, 52 warps). Grid = 1536 =
// (bc=768) x (pair-group=2). Warp w handles pair p = grp*4+w: rings p then
// 15-p, sequentially. Every warp: exactly 32 area units (~6440 px).
// Hist byte addr = (bin>>2)*128 + lane*4 + (bin&3) -> bank == lane.

__global__ void __launch_bounds__(128) k_main(const float* __restrict__ img,
                                              float* __restrict__ out) {
    __shared__ uint8_t hist[4][4096];

    const int lane = threadIdx.x & 31;
    const int w    = threadIdx.x >> 5;
    const int bc   = blockIdx.x >> 1;
    const int p    = ((blockIdx.x & 1) << 2) + w;   // pair index 0..7

    uint8_t* h = hist[w];
    const float* __restrict__ ip = img + (size_t)bc * (HH * WW);
    const int hb_lane = lane << 2;
    const int b = bc / 3, c = bc - b * 3;

    #pragma unroll
    for (int rr = 0; rr < 2; rr++) {
        const int ring = rr ? (15 - p) : p;

        // zero this warp's 4KB histogram
        uint4* h4 = (uint4*)h;
        uint4 z; z.x = z.y = z.z = z.w = 0u;
        #pragma unroll
        for (int j = 0; j < 8; j++) h4[j * 32 + lane] = z;
        __syncwarp();

        const int start = g_ringbase[ring];
        const int n     = g_ringbase[ring + 1] - start;
        const uint16_t* __restrict__ offs = g_off + start;

        // 512 px per step: 16 independent offset loads, 16 image loads
        // (MLP=16), 16 conflict-free hist updates. Predicated tail folded in.
        for (int base = 0; base < n; base += 512) {
            int o[16];
            bool pr[16];
            #pragma unroll
            for (int j = 0; j < 16; j++) {
                int i = base + j * 32 + lane;
                pr[j] = (i < n);
                o[j] = offs[pr[j] ? i : (n - 1)];
            }
            float v[16];
            #pragma unroll
            for (int j = 0; j < 16; j++) v[j] = __ldcs(ip + o[j]);
            #pragma unroll
            for (int j = 0; j < 16; j++) {
                float t = __fmul_rn(v[j], 0.5f);
                t = __fadd_rn(t, 0.5f);
                t = __fmul_rn(t, 255.0f);
                int bin = __float2int_rd(t) - 127;
                if (pr[j]) h[((bin & 0x7C) << 5) + hb_lane + (bin & 3)] += 1;
            }
        }
        __syncwarp();

        // Reduce: lane l owns bins 4l..4l+3; sum byte counters of 32 lanes.
        const uint32_t* hw = (const uint32_t*)h;
        uint32_t a02 = 0, a13 = 0;
        #pragma unroll
        for (int jj = 0; jj < 32; jj++) {
            int j = (jj + lane) & 31;
            uint32_t vv = hw[lane * 32 + j];
            a02 += vv & 0x00FF00FFu;
            a13 += (vv >> 8) & 0x00FF00FFu;
        }
        int h0 = (int)(a02 & 0xFFFFu), h2 = (int)(a02 >> 16);
        int h1 = (int)(a13 & 0xFFFFu), h3 = (int)(a13 >> 16);

        const int b0 = lane * 4;
        int sl  = h0 + h1 + h2 + h3;
        int sb  = h0 * b0 + h1 * (b0 + 1) + h2 * (b0 + 2) + h3 * (b0 + 3);
        int sb2 = h0 * b0 * b0 + h1 * (b0 + 1) * (b0 + 1)
                + h2 * (b0 + 2) * (b0 + 2) + h3 * (b0 + 3) * (b0 + 3);

        int sumb  = __reduce_add_sync(0xffffffffu, sb);
        int sumb2 = __reduce_add_sync(0xffffffffu, sb2);

        int sc = sl;
        #pragma unroll
        for (int d = 1; d < 32; d <<= 1) {
            int t2 = __shfl_up_sync(0xffffffffu, sc, d);
            if (lane >= d) sc += t2;
        }
        int cb = sc - sl;

        int k1 = (n - 1) >> 1, k2 = n >> 1;
        int c1 = 1 << 30, c2 = 1 << 30;
        {
            int t1 = k1 + 1;
            if (cb < t1 && t1 <= sc) {
                if      (cb + h0 >= t1)           c1 = b0;
                else if (cb + h0 + h1 >= t1)      c1 = b0 + 1;
                else if (cb + h0 + h1 + h2 >= t1) c1 = b0 + 2;
                else                              c1 = b0 + 3;
            }
            int t2r = k2 + 1;
            if (cb < t2r && t2r <= sc) {
                if      (cb + h0 >= t2r)           c2 = b0;
                else if (cb + h0 + h1 >= t2r)      c2 = b0 + 1;
                else if (cb + h0 + h1 + h2 >= t2r) c2 = b0 + 2;
                else                               c2 = b0 + 3;
            }
        }
        int m1 = __reduce_min_sync(0xffffffffu, c1);
        int m2 = __reduce_min_sync(0xffffffffu, c2);

        if (lane == 0) {
            double dn = (double)n;
            double mb = (double)sumb / dn;
            double mean = 127.0 + mb;
            double var = (double)sumb2 / dn - mb * mb;
            double sd = sqrt(var > 0.0 ? var : 0.0);
            double med = 127.0 + 0.5 * (double)(m1 + m2);
            int o = b * (NR * 9) + ring * 9 + c;
            out[o]     = (float)mean;
            out[o + 3] = (float)sd;
            out[o + 6] = (float)med;
        }
        __syncwarp();
    }
}

extern "C" void kernel_launch(void* const* d_in, const int* in_sizes, int n_in,
                              void* d_out, int out_size) {
    const float* img = (const float*)d_in[0];
    float* out = (float*)d_out;

    k_count<<<HH, WW>>>();
    k_prefix<<<1, 32>>>();
    k_scatter<<<HH, WW>>>();

    k_main<<<1536, 128>>>(img, out);
}

// round 4
// speedup vs baseline: 1.3400x; 1.0435x over previous
#include <cuda_runtime.h>
#include <stdint.h>

// RadialTokenizer: per (batch=256, channel=3) image 256x256:
//   img = floor((x*0.5+0.5)*255)  -> integers in [127,254] (128 bins)
//   16 rings (annuli width 8 around (128,128)): mean, std, median
// out[b, r, 0:3]=mean, [3:6]=std, [6:9]=median   (256,16,9) fp32
//
// Exact 128-bin histogram per (b,c,ring) in per-lane private byte counters
// (conflict-free, no atomics). One warp = one ring PAIR (k,15-k): every warp
// processes exactly ~6440 px -> perfect load balance.

#define HH 256
#define WW 256
#define NR 16
#define MAXPIX 53248

__device__ __align__(128) uint16_t g_off[MAXPIX];
__device__ int g_ringbase[NR + 1];   // padded starts (multiples of 64 entries)
__device__ int g_ringlen[NR];        // true pixel counts
__device__ int g_rowcnt[HH * NR];
__device__ int g_rowstart[HH * NR];

// ring i <=> 64*i^2 < d2 <= 64*(i+1)^2 ; center excluded. O(1) w/ exact fixup.
__device__ __forceinline__ int ring_of(int x, int y) {
    int dx = x - 128, dy = y - 128;
    int d2 = dx * dx + dy * dy;
    if (d2 == 0 || d2 > 16384) return -1;
    int i = (int)(__fmul_rn(sqrtf((float)d2), 0.125f) + 0.999f) - 1;  // approx
    if (i < 0) i = 0;
    while (i > 0 && 64 * i * i >= d2) i--;
    while (d2 > 64 * (i + 1) * (i + 1)) i++;
    return i;
}

// ---------------- init kernels (deterministic, run every launch) ----------------

__global__ void k_count() {
    __shared__ int cnt[NR];
    int x = threadIdx.x, y = blockIdx.x;
    int lane = x & 31;
    if (x < NR) cnt[x] = 0;
    __syncthreads();
    int r = ring_of(x, y);
    unsigned m = __match_any_sync(0xffffffffu, r);
    if (r >= 0 && (m & ((1u << lane) - 1)) == 0)
        atomicAdd(&cnt[r], __popc(m));
    __syncthreads();
    if (x < NR) g_rowcnt[y * NR + x] = cnt[x];
}

__global__ void k_prefix() {
    int t = threadIdx.x;
    __shared__ int tot[NR];
    __shared__ int base[NR];
    if (t < NR) {
        int s = 0;
        for (int y = 0; y < HH; y++) s += g_rowcnt[y * NR + t];
        tot[t] = s;
    }
    __syncthreads();
    if (t == 0) {
        int run = 0;
        for (int r = 0; r < NR; r++) {
            base[r] = run;
            g_ringbase[r] = run;
            g_ringlen[r] = tot[r];
            run += (tot[r] + 63) & ~63;   // pad to 64 entries (128B) per ring
        }
        g_ringbase[NR] = run;
    }
    __syncthreads();
    if (t < NR) {
        int run = base[t];
        for (int y = 0; y < HH; y++) {
            g_rowstart[y * NR + t] = run;
            run += g_rowcnt[y * NR + t];
        }
    }
}

__global__ void k_scatter() {
    __shared__ int wcnt[8][NR];
    __shared__ int wbase[8][NR];
    int x = threadIdx.x, y = blockIdx.x;
    int lane = x & 31, w = x >> 5;
    int r = ring_of(x, y);
    unsigned m = __match_any_sync(0xffffffffu, r);
    int rank = __popc(m & ((1u << lane) - 1));
    if (x < 8 * NR) ((int*)wcnt)[x] = 0;
    __syncthreads();
    if (r >= 0 && rank == 0) wcnt[w][r] = __popc(m);
    __syncthreads();
    if (x < NR) {
        int run = 0;
        #pragma unroll
        for (int ww = 0; ww < 8; ww++) { wbase[ww][x] = run; run += wcnt[ww][x]; }
    }
    __syncthreads();
    if (r >= 0)
        g_off[g_rowstart[y * NR + r] + wbase[w][r] + rank] = (uint16_t)(y * WW + x);
}

// ---------------- main kernel ----------------
// Block = 4 warps (16KB smem). Grid = 1536 = (bc=768) x (pair-group=2).
// Warp w handles pair p = grp*4+w: rings p then 15-p sequentially.
// Hist byte addr = ((bin<<5)&0xF80) | (lane<<2) | (bin&3)  -> bank == lane.

__global__ void __launch_bounds__(128) k_main(const float* __restrict__ img,
                                              float* __restrict__ out) {
    __shared__ uint8_t hist[4][4096];

    const int lane = threadIdx.x & 31;
    const int w    = threadIdx.x >> 5;
    const int bc   = blockIdx.x >> 1;
    const int p    = ((blockIdx.x & 1) << 2) + w;   // pair index 0..7

    uint8_t* h = hist[w];
    const float* __restrict__ ip = img + (size_t)bc * (HH * WW);
    const int hb_lane = lane << 2;
    const int b = bc / 3, c = bc - b * 3;

    #pragma unroll
    for (int rr = 0; rr < 2; rr++) {
        const int ring = rr ? (15 - p) : p;

        // zero this warp's 4KB histogram
        uint4* h4 = (uint4*)h;
        uint4 z; z.x = z.y = z.z = z.w = 0u;
        #pragma unroll
        for (int j = 0; j < 8; j++) h4[j * 32 + lane] = z;
        __syncwarp();

        const int start = g_ringbase[ring];      // multiple of 64
        const int n     = g_ringlen[ring];
        const uint16_t* __restrict__ offs = g_off + start;
        const uint32_t* __restrict__ offs32 = (const uint32_t*)offs;

        // Main loop: 256 px/step. 4 packed u32 offset loads -> 8 independent
        // image loads (MLP=8) -> 8 conflict-free hist updates. No predication.
        const int nfull = n & ~255;
        for (int base = 0; base < nfull; base += 256) {
            uint32_t ow[4];
            #pragma unroll
            for (int j = 0; j < 4; j++)
                ow[j] = offs32[(base >> 1) + j * 32 + lane];
            float v[8];
            #pragma unroll
            for (int j = 0; j < 4; j++) {
                v[2 * j]     = __ldcs(ip + (ow[j] & 0xFFFFu));
                v[2 * j + 1] = __ldcs(ip + (ow[j] >> 16));
            }
            #pragma unroll
            for (int j = 0; j < 8; j++) {
                float t = __fmul_rn(v[j], 0.5f);
                t = __fadd_rn(t, 0.5f);
                t = __fmul_rn(t, 255.0f);
                int bin = __float2int_rd(t) - 127;
                h[((bin << 5) & 0xF80) | hb_lane | (bin & 3)] += 1;
            }
        }
        // tail (< 256 px)
        for (int i = nfull + lane; i < n; i += 32) {
            int off = offs[i];
            float t = __fmul_rn(__ldcs(ip + off), 0.5f);
            t = __fadd_rn(t, 0.5f);
            t = __fmul_rn(t, 255.0f);
            int bin = __float2int_rd(t) - 127;
            h[((bin << 5) & 0xF80) | hb_lane | (bin & 3)] += 1;
        }
        __syncwarp();

        // Reduce: lane l owns bins 4l..4l+3; sum byte counters of 32 lanes.
        const uint32_t* hw = (const uint32_t*)h;
        uint32_t a02 = 0, a13 = 0;
        #pragma unroll
        for (int jj = 0; jj < 32; jj++) {
            int j = (jj + lane) & 31;
            uint32_t vv = hw[lane * 32 + j];
            a02 += vv & 0x00FF00FFu;
            a13 += (vv >> 8) & 0x00FF00FFu;
        }
        int h0 = (int)(a02 & 0xFFFFu), h2 = (int)(a02 >> 16);
        int h1 = (int)(a13 & 0xFFFFu), h3 = (int)(a13 >> 16);

        const int b0 = lane * 4;
        int sl  = h0 + h1 + h2 + h3;
        int sb  = h0 * b0 + h1 * (b0 + 1) + h2 * (b0 + 2) + h3 * (b0 + 3);
        int sb2 = h0 * b0 * b0 + h1 * (b0 + 1) * (b0 + 1)
                + h2 * (b0 + 2) * (b0 + 2) + h3 * (b0 + 3) * (b0 + 3);

        int sumb  = __reduce_add_sync(0xffffffffu, sb);
        int sumb2 = __reduce_add_sync(0xffffffffu, sb2);

        int sc = sl;
        #pragma unroll
        for (int d = 1; d < 32; d <<= 1) {
            int t2 = __shfl_up_sync(0xffffffffu, sc, d);
            if (lane >= d) sc += t2;
        }
        int cb = sc - sl;

        int k1 = (n - 1) >> 1, k2 = n >> 1;
        int c1 = 1 << 30, c2 = 1 << 30;
        {
            int t1 = k1 + 1;
            if (cb < t1 && t1 <= sc) {
                if      (cb + h0 >= t1)           c1 = b0;
                else if (cb + h0 + h1 >= t1)      c1 = b0 + 1;
                else if (cb + h0 + h1 + h2 >= t1) c1 = b0 + 2;
                else                              c1 = b0 + 3;
            }
            int t2r = k2 + 1;
            if (cb < t2r && t2r <= sc) {
                if      (cb + h0 >= t2r)           c2 = b0;
                else if (cb + h0 + h1 >= t2r)      c2 = b0 + 1;
                else if (cb + h0 + h1 + h2 >= t2r) c2 = b0 + 2;
                else                               c2 = b0 + 3;
            }
        }
        int m1 = __reduce_min_sync(0xffffffffu, c1);
        int m2 = __reduce_min_sync(0xffffffffu, c2);

        if (lane == 0) {
            double dn = (double)n;
            double mb = (double)sumb / dn;
            double mean = 127.0 + mb;
            double var = (double)sumb2 / dn - mb * mb;
            double sd = sqrt(var > 0.0 ? var : 0.0);
            double med = 127.0 + 0.5 * (double)(m1 + m2);
            int o = b * (NR * 9) + ring * 9 + c;
            out[o]     = (float)mean;
            out[o + 3] = (float)sd;
            out[o + 6] = (float)med;
        }
        __syncwarp();
    }
}

extern "C" void kernel_launch(void* const* d_in, const int* in_sizes, int n_in,
                              void* d_out, int out_size) {
    const float* img = (const float*)d_in[0];
    float* out = (float*)d_out;

    k_count<<<HH, WW>>>();
    k_prefix<<<1, 32>>>();
    k_scatter<<<HH, WW>>>();

    k_main<<<1536, 128>>>(img, out);
}